// round 7
// baseline (speedup 1.0000x reference)
#include <cuda_runtime.h>
#include <math.h>

// KAN FFN: y2 = KAN2(KAN1(x)), each layer = feature-expansion (silu + 6 cubic
// B-spline basis funcs on a uniform grid) followed by a GEMM.
//
// Register-blocked fused GEMM (first bench attempt of this design):
//  - thread tile: 4 rows x 8 outs (4 f32x2 output-pairs x 4 rows)
//  - features stored in smem pre-duplicated (f,f) -> FFMA2 lanes share them
//  - weights preprocessed into packed (w[2p],w[2p+1]) pairs, g-major layout
//    [IN][7][OUT/2] -> fully coalesced LDG.128 streams (L2 resident)

#define D_MODEL 1024
#define KAN_HIDDEN 128

typedef unsigned long long ull;

// ---- device scratch (allocation-free rule) ----
__device__ float g_y1[16384 * KAN_HIDDEN];                 // inter-layer acts
__device__ ull g_w1[(size_t)D_MODEL * 7 * (KAN_HIDDEN / 2)]; // packed weights L1
__device__ ull g_w2[(size_t)KAN_HIDDEN * 7 * (D_MODEL / 2)]; // packed weights L2

// ---------------- packed f32x2 helpers ----------------
__device__ __forceinline__ ull pack2(float lo, float hi) {
    ull r;
    asm("mov.b64 %0, {%1, %2};" : "=l"(r) : "f"(lo), "f"(hi));
    return r;
}
__device__ __forceinline__ ull ffma2(ull a, ull b, ull c) {
    ull d;
    asm("fma.rn.f32x2 %0, %1, %2, %3;" : "=l"(d) : "l"(a), "l"(b), "l"(c));
    return d;
}

// ---------------- feature computation ----------------
// Uniform knots t[j] = (j-3)*(2/3) - 1; Cox-de Boor with constant denominators.
__device__ __forceinline__ void kan_features(float x, float f[7]) {
    const float h = 2.0f / 3.0f;
    float t[10];
#pragma unroll
    for (int j = 0; j < 10; ++j) t[j] = (float)(j - 3) * h - 1.0f;

    float B[9];
#pragma unroll
    for (int j = 0; j < 9; ++j)
        B[j] = (x >= t[j] && x < t[j + 1]) ? 1.0f : 0.0f;

#pragma unroll
    for (int d = 1; d <= 3; ++d) {
#pragma unroll
        for (int j = 0; j < 9 - d; ++j) {
            float invL = 1.0f / (t[j + d] - t[j]);
            float invR = 1.0f / (t[j + d + 1] - t[j + 1]);
            B[j] = (x - t[j]) * invL * B[j] + (t[j + d + 1] - x) * invR * B[j + 1];
        }
    }

    float sg = 1.0f / (1.0f + expf(-x));
    f[0] = x * sg;
#pragma unroll
    for (int g = 0; g < 6; ++g) f[1 + g] = B[g];
}

// ---------------- weight preprocessing ----------------
// wpack[(i*7+g)*OUT/2 + p] = pack2(w(2p,g), w(2p+1,g))
// w(o,0)=scale_base[i,o]; w(o,g)=coef[i,o,g-1]*scale_sp[i,o]
__global__ void prep_kernel(const float* __restrict__ coef,
                            const float* __restrict__ sb,
                            const float* __restrict__ ssp,
                            ull* __restrict__ wpack, int IN, int OUT) {
    int idx = blockIdx.x * blockDim.x + threadIdx.x;
    int HP = OUT >> 1;
    if (idx >= IN * HP) return;
    int i = idx / HP, p = idx - i * HP;
    int wi0 = i * OUT + 2 * p;
    float s0 = ssp[wi0], s1 = ssp[wi0 + 1];
    ull* wp = wpack + (size_t)i * 7 * HP + p;
    wp[0] = pack2(sb[wi0], sb[wi0 + 1]);
    const float* c0 = coef + (size_t)wi0 * 6;
#pragma unroll
    for (int g = 0; g < 6; ++g)
        wp[(size_t)(g + 1) * HP] = pack2(c0[g] * s0, c0[6 + g] * s1);
}

// ---------------- fused KAN layer GEMM ----------------
// Block: 256 threads. Tile: 64 rows x 128 outs. og = tid&15 (4 out-pairs each),
// rg = tid>>4 (4 rows each). i processed in chunks of IC=8 via smem features.
template <int IN, int OUT>
__global__ void __launch_bounds__(256, 2)
kan_gemm_kernel(const float* __restrict__ X,      // [N, IN]
                const ull* __restrict__ wpack,    // [IN][7][OUT/2]
                float* __restrict__ Y,            // [N, OUT]
                int N) {
    constexpr int TR = 64;
    constexpr int IC = 8;
    constexpr int HP = OUT / 2;
    constexpr int GST = 66;                       // padded row stride (ull)

    __shared__ __align__(16) ull sfeat[IC * 7 * GST];  // 29568 B

    const int tid = threadIdx.x;
    const int rowBase = blockIdx.x * TR;
    const int pairBase = blockIdx.y * 64;

    const int og = tid & 15;        // out-pair group: pairs og*4 .. og*4+3
    const int rg = tid >> 4;        // row group: rows rg*4 .. rg*4+3

    // featurize mapping: thread -> (row, 2 consecutive i)
    const int frow = tid >> 2;
    const int fio = (tid & 3) * 2;

    ull acc[4][4];                  // [out-pair p][row r]
#pragma unroll
    for (int p = 0; p < 4; ++p)
#pragma unroll
        for (int r = 0; r < 4; ++r) acc[p][r] = 0ull;

    for (int i0 = 0; i0 < IN; i0 += IC) {
        __syncthreads();

        // ---- featurize: 64 rows x 8 i -> duplicated (f,f) pairs in smem ----
        {
            const float2 xv = *reinterpret_cast<const float2*>(
                &X[(size_t)(rowBase + frow) * IN + i0 + fio]);
            float f[7];
            kan_features(xv.x, f);
#pragma unroll
            for (int g = 0; g < 7; ++g)
                sfeat[((fio + 0) * 7 + g) * GST + frow] = pack2(f[g], f[g]);
            kan_features(xv.y, f);
#pragma unroll
            for (int g = 0; g < 7; ++g)
                sfeat[((fio + 1) * 7 + g) * GST + frow] = pack2(f[g], f[g]);
        }
        __syncthreads();

        // ---- compute ----
#pragma unroll 1
        for (int ii = 0; ii < IC; ++ii) {
            const ull* wp =
                wpack + (size_t)(i0 + ii) * 7 * HP + pairBase + og * 4;
            const ull* fp = sfeat + ii * 7 * GST + rg * 4;
#pragma unroll
            for (int g = 0; g < 7; ++g) {
                const ulonglong2 w01 =
                    *reinterpret_cast<const ulonglong2*>(wp + (size_t)g * HP);
                const ulonglong2 w23 =
                    *reinterpret_cast<const ulonglong2*>(wp + (size_t)g * HP + 2);
                const ulonglong2 f01 =
                    *reinterpret_cast<const ulonglong2*>(fp + g * GST);
                const ulonglong2 f23 =
                    *reinterpret_cast<const ulonglong2*>(fp + g * GST + 2);

                acc[0][0] = ffma2(f01.x, w01.x, acc[0][0]);
                acc[0][1] = ffma2(f01.y, w01.x, acc[0][1]);
                acc[0][2] = ffma2(f23.x, w01.x, acc[0][2]);
                acc[0][3] = ffma2(f23.y, w01.x, acc[0][3]);
                acc[1][0] = ffma2(f01.x, w01.y, acc[1][0]);
                acc[1][1] = ffma2(f01.y, w01.y, acc[1][1]);
                acc[1][2] = ffma2(f23.x, w01.y, acc[1][2]);
                acc[1][3] = ffma2(f23.y, w01.y, acc[1][3]);
                acc[2][0] = ffma2(f01.x, w23.x, acc[2][0]);
                acc[2][1] = ffma2(f01.y, w23.x, acc[2][1]);
                acc[2][2] = ffma2(f23.x, w23.x, acc[2][2]);
                acc[2][3] = ffma2(f23.y, w23.x, acc[2][3]);
                acc[3][0] = ffma2(f01.x, w23.y, acc[3][0]);
                acc[3][1] = ffma2(f01.y, w23.y, acc[3][1]);
                acc[3][2] = ffma2(f23.x, w23.y, acc[3][2]);
                acc[3][3] = ffma2(f23.y, w23.y, acc[3][3]);
            }
        }
    }

    // ---- epilogue: packed pairs are (o even, o odd) -> store as vectors ----
    const int oBase = 2 * (pairBase + og * 4);   // 8 consecutive outs
#pragma unroll
    for (int r = 0; r < 4; ++r) {
        const size_t row = rowBase + rg * 4 + r;
        ulonglong2 v01, v23;
        v01.x = acc[0][r]; v01.y = acc[1][r];
        v23.x = acc[2][r]; v23.y = acc[3][r];
        *reinterpret_cast<ulonglong2*>(&Y[row * OUT + oBase]) = v01;
        *reinterpret_cast<ulonglong2*>(&Y[row * OUT + oBase + 4]) = v23;
    }
}

// ---------------- launcher ----------------
extern "C" void kernel_launch(void* const* d_in, const int* in_sizes, int n_in,
                              void* d_out, int out_size) {
    const float* x     = (const float*)d_in[0];
    const float* coef1 = (const float*)d_in[1];
    const float* sb1   = (const float*)d_in[2];
    const float* ssp1  = (const float*)d_in[3];
    const float* coef2 = (const float*)d_in[4];
    const float* sb2   = (const float*)d_in[5];
    const float* ssp2  = (const float*)d_in[6];
    float* out = (float*)d_out;

    const int N = in_sizes[0] / D_MODEL;   // 16384

    float* y1 = nullptr;
    ull *w1 = nullptr, *w2 = nullptr;
    cudaGetSymbolAddress((void**)&y1, g_y1);
    cudaGetSymbolAddress((void**)&w1, g_w1);
    cudaGetSymbolAddress((void**)&w2, g_w2);

    // weight preprocessing (tiny)
    {
        int n1 = D_MODEL * (KAN_HIDDEN / 2);
        prep_kernel<<<(n1 + 255) / 256, 256>>>(coef1, sb1, ssp1, w1, D_MODEL,
                                               KAN_HIDDEN);
        int n2 = KAN_HIDDEN * (D_MODEL / 2);
        prep_kernel<<<(n2 + 255) / 256, 256>>>(coef2, sb2, ssp2, w2, KAN_HIDDEN,
                                               D_MODEL);
    }

    // Layer 1: 1024 -> 128
    kan_gemm_kernel<D_MODEL, KAN_HIDDEN>
        <<<dim3(N / 64, KAN_HIDDEN / 128), 256>>>(x, w1, y1, N);
    // Layer 2: 128 -> 1024
    kan_gemm_kernel<KAN_HIDDEN, D_MODEL>
        <<<dim3(N / 64, D_MODEL / 128), 256>>>(y1, w2, out, N);
}